// round 1
// baseline (speedup 1.0000x reference)
#include <cuda_runtime.h>
#include <cuda_bf16.h>
#include <cstdint>
#include <cstdio>

// Problem constants
#define NB   4
#define LSEQ 8192
#define EMB  512
#define HEADS 8
#define HDIM 64
#define BS   128
#define ABLK 64          // LSEQ / BS
#define FFD  1024        // 2*EMB
#define MROWS (NB*LSEQ)  // 32768

// ---------------------------------------------------------------------------
// Scratch (static device allocations; no cudaMalloc allowed)
// ---------------------------------------------------------------------------
__device__ float g_v  [MROWS * EMB];
__device__ float g_k  [MROWS * EMB];
__device__ float g_q  [MROWS * EMB];
__device__ float g_att[MROWS * EMB];
__device__ float g_tmp[MROWS * EMB];
__device__ float g_x  [MROWS * EMB];
__device__ float g_ff [MROWS * FFD];

// ---------------------------------------------------------------------------
// SGEMM: C[M,Nn] = A[M,K] @ B[K,Nn] + bias (+ optional exact GELU)
// BM=BN=128, BK=16, 256 threads, 8x8 microtile, A transposed in smem.
// ---------------------------------------------------------------------------
#define BKG 16

template<int DO_GELU>
__global__ __launch_bounds__(256, 2)
void sgemm_bias(const float* __restrict__ A, const float* __restrict__ B,
                const float* __restrict__ bias, float* __restrict__ C,
                int M, int Nn, int K)
{
    __shared__ float As[BKG][132];   // padded to reduce store conflicts
    __shared__ float Bs[BKG][128];

    const int tid = threadIdx.x;
    const int tx  = tid & 15;
    const int ty  = tid >> 4;
    const int m0  = blockIdx.y * 128;
    const int n0  = blockIdx.x * 128;

    // A tile loads: 128x16 = 512 float4, 2 per thread
    const int aRow0 = tid >> 2;             // 0..63
    const int aC0   = (tid & 3) * 4;        // k offset 0,4,8,12
    const int aRow1 = aRow0 + 64;
    // B tile loads: 16x128 = 512 float4, 2 per thread
    const int bR0 = tid >> 5;               // 0..7
    const int bC0 = (tid & 31) * 4;         // 0..124
    const int bR1 = bR0 + 8;

    const float* Aptr = A + (size_t)m0 * K;
    const float* Bptr = B + n0;

    float4 pa0, pa1, pb0, pb1;
    pa0 = *(const float4*)(Aptr + (size_t)aRow0 * K + aC0);
    pa1 = *(const float4*)(Aptr + (size_t)aRow1 * K + aC0);
    pb0 = *(const float4*)(Bptr + (size_t)bR0 * Nn + bC0);
    pb1 = *(const float4*)(Bptr + (size_t)bR1 * Nn + bC0);

    float acc[8][8];
    #pragma unroll
    for (int i = 0; i < 8; i++)
        #pragma unroll
        for (int j = 0; j < 8; j++) acc[i][j] = 0.f;

    const int nK = K / BKG;
    for (int kt = 0; kt < nK; kt++) {
        __syncthreads();
        // store A transposed
        As[aC0 + 0][aRow0] = pa0.x;
        As[aC0 + 1][aRow0] = pa0.y;
        As[aC0 + 2][aRow0] = pa0.z;
        As[aC0 + 3][aRow0] = pa0.w;
        As[aC0 + 0][aRow1] = pa1.x;
        As[aC0 + 1][aRow1] = pa1.y;
        As[aC0 + 2][aRow1] = pa1.z;
        As[aC0 + 3][aRow1] = pa1.w;
        *(float4*)&Bs[bR0][bC0] = pb0;
        *(float4*)&Bs[bR1][bC0] = pb1;
        __syncthreads();

        if (kt + 1 < nK) {
            int k0 = (kt + 1) * BKG;
            pa0 = *(const float4*)(Aptr + (size_t)aRow0 * K + k0 + aC0);
            pa1 = *(const float4*)(Aptr + (size_t)aRow1 * K + k0 + aC0);
            pb0 = *(const float4*)(Bptr + (size_t)(k0 + bR0) * Nn + bC0);
            pb1 = *(const float4*)(Bptr + (size_t)(k0 + bR1) * Nn + bC0);
        }

        #pragma unroll
        for (int kk = 0; kk < BKG; kk++) {
            float rm[8], rn[8];
            *(float4*)&rm[0] = *(const float4*)&As[kk][ty * 8];
            *(float4*)&rm[4] = *(const float4*)&As[kk][ty * 8 + 4];
            *(float4*)&rn[0] = *(const float4*)&Bs[kk][tx * 8];
            *(float4*)&rn[4] = *(const float4*)&Bs[kk][tx * 8 + 4];
            #pragma unroll
            for (int i = 0; i < 8; i++)
                #pragma unroll
                for (int j = 0; j < 8; j++)
                    acc[i][j] += rm[i] * rn[j];
        }
    }

    // epilogue
    float bv[8];
    #pragma unroll
    for (int j = 0; j < 8; j++) bv[j] = bias[n0 + tx * 8 + j];

    #pragma unroll
    for (int i = 0; i < 8; i++) {
        const int m = m0 + ty * 8 + i;
        float r[8];
        #pragma unroll
        for (int j = 0; j < 8; j++) {
            float c = acc[i][j] + bv[j];
            if (DO_GELU) c = 0.5f * c * (1.f + erff(c * 0.70710678118654752f));
            r[j] = c;
        }
        float* Cp = C + (size_t)m * Nn + n0 + tx * 8;
        *(float4*)&Cp[0] = *(float4*)&r[0];
        *(float4*)&Cp[4] = *(float4*)&r[4];
    }
}

// ---------------------------------------------------------------------------
// Block-diagonal attention: one CTA per (head, block, batch)
// Q,K,V in [N*L, E] layout; head slice via column offset h*64.
// smem: Qt[64][128] | Kt[64][128] | Vs[128][64] | S[128][129]
// ---------------------------------------------------------------------------
#define ATT_SMEM_FLOATS (8192*3 + 128*129)

__global__ __launch_bounds__(256, 1)
void attn_kernel(const float* __restrict__ Q, const float* __restrict__ K,
                 const float* __restrict__ V, const int* __restrict__ mask,
                 float* __restrict__ O)
{
    extern __shared__ float sm[];
    float* Qt = sm;             // [64][128]
    float* Kt = sm + 8192;      // [64][128]
    float* Vs = sm + 16384;     // [128][64]
    float* S  = sm + 24576;     // [128][129]

    const int h = blockIdx.x, a = blockIdx.y, n = blockIdx.z;
    const int tid = threadIdx.x;
    const int tx = tid & 15, ty = tid >> 4;
    const size_t base = ((size_t)n * LSEQ + (size_t)a * BS) * EMB + h * HDIM;

    // load Q,K transposed; V direct. 128 rows x 16 float4 = 2048 f4, 8/thread
    #pragma unroll
    for (int i = 0; i < 8; i++) {
        int id = tid + i * 256;
        int r  = id >> 4;        // 0..127
        int d  = (id & 15) * 4;  // 0..60
        float4 q4 = *(const float4*)(Q + base + (size_t)r * EMB + d);
        float4 k4 = *(const float4*)(K + base + (size_t)r * EMB + d);
        float4 v4 = *(const float4*)(V + base + (size_t)r * EMB + d);
        Qt[(d + 0) * 128 + r] = q4.x;
        Qt[(d + 1) * 128 + r] = q4.y;
        Qt[(d + 2) * 128 + r] = q4.z;
        Qt[(d + 3) * 128 + r] = q4.w;
        Kt[(d + 0) * 128 + r] = k4.x;
        Kt[(d + 1) * 128 + r] = k4.y;
        Kt[(d + 2) * 128 + r] = k4.z;
        Kt[(d + 3) * 128 + r] = k4.w;
        *(float4*)&Vs[r * 64 + d] = v4;
    }
    __syncthreads();

    // S = Q @ K^T   (8x8 microtile per thread)
    {
        float acc[8][8];
        #pragma unroll
        for (int i = 0; i < 8; i++)
            #pragma unroll
            for (int j = 0; j < 8; j++) acc[i][j] = 0.f;

        #pragma unroll 4
        for (int d = 0; d < 64; d++) {
            float rq[8], rk[8];
            *(float4*)&rq[0] = *(const float4*)&Qt[d * 128 + ty * 8];
            *(float4*)&rq[4] = *(const float4*)&Qt[d * 128 + ty * 8 + 4];
            *(float4*)&rk[0] = *(const float4*)&Kt[d * 128 + tx * 8];
            *(float4*)&rk[4] = *(const float4*)&Kt[d * 128 + tx * 8 + 4];
            #pragma unroll
            for (int i = 0; i < 8; i++)
                #pragma unroll
                for (int j = 0; j < 8; j++)
                    acc[i][j] += rq[i] * rk[j];
        }
        #pragma unroll
        for (int i = 0; i < 8; i++)
            #pragma unroll
            for (int j = 0; j < 8; j++)
                S[(ty * 8 + i) * 129 + tx * 8 + j] = acc[i][j];
    }
    __syncthreads();

    // softmax per row (8 warps x 16 rows), mask + 1/sqrt(64) scale
    {
        const int* mrow = mask + n * (BS * BS);
        const int w = tid >> 5, lane = tid & 31;
        for (int rr = 0; rr < 16; rr++) {
            const int r = w * 16 + rr;
            float x[4];
            #pragma unroll
            for (int j = 0; j < 4; j++) {
                int k = lane + j * 32;
                float s = S[r * 129 + k];
                x[j] = mrow[r * BS + k] ? s * 0.125f : -1e20f;
            }
            float mx = fmaxf(fmaxf(x[0], x[1]), fmaxf(x[2], x[3]));
            #pragma unroll
            for (int off = 16; off >= 1; off >>= 1)
                mx = fmaxf(mx, __shfl_xor_sync(0xffffffffu, mx, off));
            float e[4], sum = 0.f;
            #pragma unroll
            for (int j = 0; j < 4; j++) { e[j] = __expf(x[j] - mx); sum += e[j]; }
            #pragma unroll
            for (int off = 16; off >= 1; off >>= 1)
                sum += __shfl_xor_sync(0xffffffffu, sum, off);
            float inv = 1.f / sum;
            #pragma unroll
            for (int j = 0; j < 4; j++)
                S[r * 129 + lane + j * 32] = e[j] * inv;
        }
    }
    __syncthreads();

    // O = P @ V : thread computes 8 rows x 4 cols
    {
        float o[8][4];
        #pragma unroll
        for (int i = 0; i < 8; i++)
            #pragma unroll
            for (int j = 0; j < 4; j++) o[i][j] = 0.f;

        #pragma unroll 2
        for (int k = 0; k < 128; k++) {
            float rv[4];
            *(float4*)&rv[0] = *(const float4*)&Vs[k * 64 + tx * 4];
            float rp[8];
            #pragma unroll
            for (int i = 0; i < 8; i++) rp[i] = S[(ty * 8 + i) * 129 + k];
            #pragma unroll
            for (int i = 0; i < 8; i++)
                #pragma unroll
                for (int j = 0; j < 4; j++)
                    o[i][j] += rp[i] * rv[j];
        }
        #pragma unroll
        for (int i = 0; i < 8; i++) {
            int q = ty * 8 + i;
            float* Op = O + base + (size_t)q * EMB + tx * 4;
            *(float4*)Op = *(float4*)&o[i][0];
        }
    }
}

// ---------------------------------------------------------------------------
// Fused residual-add + LayerNorm: out = LN(A + R) * g + b
// one block (128 thr) per row of 512
// ---------------------------------------------------------------------------
__global__ __launch_bounds__(128)
void ln_kernel(const float* __restrict__ A, const float* __restrict__ R,
               const float* __restrict__ g, const float* __restrict__ b,
               float* __restrict__ out)
{
    __shared__ float red[8];
    const int row = blockIdx.x;
    const int t = threadIdx.x;
    const int lane = t & 31, w = t >> 5;

    float4 x = ((const float4*)(A + (size_t)row * EMB))[t];
    float4 y = ((const float4*)(R + (size_t)row * EMB))[t];
    x.x += y.x; x.y += y.y; x.z += y.z; x.w += y.w;

    float s  = x.x + x.y + x.z + x.w;
    float sq = x.x * x.x + x.y * x.y + x.z * x.z + x.w * x.w;
    #pragma unroll
    for (int off = 16; off >= 1; off >>= 1) {
        s  += __shfl_xor_sync(0xffffffffu, s,  off);
        sq += __shfl_xor_sync(0xffffffffu, sq, off);
    }
    if (lane == 0) { red[w] = s; red[4 + w] = sq; }
    __syncthreads();
    float S  = red[0] + red[1] + red[2] + red[3];
    float SQ = red[4] + red[5] + red[6] + red[7];
    float mean = S * (1.f / EMB);
    float var  = SQ * (1.f / EMB) - mean * mean;
    float rstd = rsqrtf(var + 1e-5f);

    float4 gg = ((const float4*)g)[t];
    float4 bb = ((const float4*)b)[t];
    float4 o;
    o.x = (x.x - mean) * rstd * gg.x + bb.x;
    o.y = (x.y - mean) * rstd * gg.y + bb.y;
    o.z = (x.z - mean) * rstd * gg.z + bb.z;
    o.w = (x.w - mean) * rstd * gg.w + bb.w;
    ((float4*)(out + (size_t)row * EMB))[t] = o;
}

// ---------------------------------------------------------------------------
// Launch
// ---------------------------------------------------------------------------
extern "C" void kernel_launch(void* const* d_in, const int* in_sizes, int n_in,
                              void* d_out, int out_size)
{
    const float* value = (const float*)d_in[0];
    const float* key   = (const float*)d_in[1];
    const float* query = (const float*)d_in[2];
    const int*   mask  = (const int*)  d_in[3];
    const float* wv = (const float*)d_in[4];
    const float* bv = (const float*)d_in[5];
    const float* wk = (const float*)d_in[6];
    const float* bk = (const float*)d_in[7];
    const float* wq = (const float*)d_in[8];
    const float* bq = (const float*)d_in[9];
    const float* wo = (const float*)d_in[10];
    const float* bo = (const float*)d_in[11];
    const float* g1 = (const float*)d_in[12];
    const float* b1 = (const float*)d_in[13];
    const float* w1 = (const float*)d_in[14];
    const float* bf1 = (const float*)d_in[15];
    const float* w2 = (const float*)d_in[16];
    const float* bf2 = (const float*)d_in[17];
    const float* g2 = (const float*)d_in[18];
    const float* b2 = (const float*)d_in[19];
    float* out = (float*)d_out;

    float *gv, *gk, *gq, *gatt, *gtmp, *gx, *gff;
    cudaGetSymbolAddress((void**)&gv,   g_v);
    cudaGetSymbolAddress((void**)&gk,   g_k);
    cudaGetSymbolAddress((void**)&gq,   g_q);
    cudaGetSymbolAddress((void**)&gatt, g_att);
    cudaGetSymbolAddress((void**)&gtmp, g_tmp);
    cudaGetSymbolAddress((void**)&gx,   g_x);
    cudaGetSymbolAddress((void**)&gff,  g_ff);

    cudaFuncSetAttribute(attn_kernel,
                         cudaFuncAttributeMaxDynamicSharedMemorySize,
                         ATT_SMEM_FLOATS * (int)sizeof(float));

    dim3 gProj(EMB / 128, MROWS / 128);   // (4, 256)
    dim3 gFF1 (FFD / 128, MROWS / 128);   // (8, 256)
    dim3 gFF2 (EMB / 128, MROWS / 128);

    // QKV projections
    sgemm_bias<0><<<gProj, 256>>>(value, wv, bv, gv, MROWS, EMB, EMB);
    sgemm_bias<0><<<gProj, 256>>>(key,   wk, bk, gk, MROWS, EMB, EMB);
    sgemm_bias<0><<<gProj, 256>>>(query, wq, bq, gq, MROWS, EMB, EMB);

    // block attention
    dim3 gAtt(HEADS, ABLK, NB);
    attn_kernel<<<gAtt, 256, ATT_SMEM_FLOATS * sizeof(float)>>>(gq, gk, gv, mask, gatt);

    // output projection + LN1(out + query)
    sgemm_bias<0><<<gProj, 256>>>(gatt, wo, bo, gtmp, MROWS, EMB, EMB);
    ln_kernel<<<MROWS, 128>>>(gtmp, query, g1, b1, gx);

    // FFN: gelu(x@w1+bf1) @ w2 + bf2 + x, then LN2
    sgemm_bias<1><<<gFF1, 256>>>(gx, w1, bf1, gff, MROWS, FFD, EMB);
    sgemm_bias<0><<<gFF2, 256>>>(gff, w2, bf2, gtmp, MROWS, EMB, FFD);
    ln_kernel<<<MROWS, 128>>>(gtmp, gx, g2, b2, out);
}

// round 2
// speedup vs baseline: 2.5059x; 2.5059x over previous
#include <cuda_runtime.h>
#include <cuda_bf16.h>
#include <cstdint>
#include <cstdio>

// Problem constants
#define NB   4
#define LSEQ 8192
#define EMB  512
#define HEADS 8
#define HDIM 64
#define BS   128
#define ABLK 64          // LSEQ / BS
#define FFD  1024        // 2*EMB
#define MROWS (NB*LSEQ)  // 32768

// ---------------------------------------------------------------------------
// Scratch (static device allocations; no cudaMalloc allowed)
// ---------------------------------------------------------------------------
__device__ float g_v  [MROWS * EMB];
__device__ float g_k  [MROWS * EMB];
__device__ float g_q  [MROWS * EMB];
__device__ float g_att[MROWS * EMB];
__device__ float g_tmp[MROWS * EMB];
__device__ float g_x  [MROWS * EMB];
__device__ float g_ff [MROWS * FFD];

// ---------------------------------------------------------------------------
// tf32 helpers
// ---------------------------------------------------------------------------
__device__ __forceinline__ unsigned f2tf32(float x) {
    unsigned u;
    asm("cvt.rna.tf32.f32 %0, %1;" : "=r"(u) : "f"(x));
    return u;
}

__device__ __forceinline__ void mma_tf32(float c[4],
                                         const unsigned a[4],
                                         const unsigned b[2]) {
    asm volatile(
        "mma.sync.aligned.m16n8k8.row.col.f32.tf32.tf32.f32 "
        "{%0,%1,%2,%3}, {%4,%5,%6,%7}, {%8,%9}, {%0,%1,%2,%3};"
        : "+f"(c[0]), "+f"(c[1]), "+f"(c[2]), "+f"(c[3])
        : "r"(a[0]), "r"(a[1]), "r"(a[2]), "r"(a[3]),
          "r"(b[0]), "r"(b[1]));
}

// ---------------------------------------------------------------------------
// TF32 tensor-core GEMM: C[M,Nn] = A[M,K] @ B[K,Nn] + bias (+ optional GELU)
// BM=BN=128, BK=16, 256 threads (8 warps, 2x4), warp tile 64x32,
// 16x m16n8k8 mma per warp per k-step. fp32 accumulate.
// Smem: As[128][20] (row-major, pad->conflict-free frag loads),
//       Bs[16][136]  (k-major,  pad->conflict-free frag loads).
// ---------------------------------------------------------------------------
template<int DO_GELU>
__global__ __launch_bounds__(256)
void tgemm_bias(const float* __restrict__ A, const float* __restrict__ B,
                const float* __restrict__ bias, float* __restrict__ C,
                int M, int Nn, int K)
{
    __shared__ unsigned As[128][20];
    __shared__ unsigned Bs[16][136];

    const int tid  = threadIdx.x;
    const int lane = tid & 31;
    const int warp = tid >> 5;
    const int wm   = warp >> 2;       // 0..1
    const int wn   = warp & 3;        // 0..3
    const int g    = lane >> 2;       // 0..7
    const int t    = lane & 3;        // 0..3

    const int m0 = blockIdx.y * 128;
    const int n0 = blockIdx.x * 128;

    // A tile global loads: 128x16 = 512 float4, 2 per thread
    const int aRow0 = tid >> 2;          // 0..63
    const int aC0   = (tid & 3) * 4;     // 0,4,8,12
    const int aRow1 = aRow0 + 64;
    // B tile global loads: 16x128 = 512 float4, 2 per thread
    const int bR0 = tid >> 5;            // 0..7
    const int bC0 = (tid & 31) * 4;      // 0..124
    const int bR1 = bR0 + 8;

    const float* Aptr = A + (size_t)m0 * K;
    const float* Bptr = B + n0;

    float4 pa0, pa1, pb0, pb1;
    pa0 = *(const float4*)(Aptr + (size_t)aRow0 * K + aC0);
    pa1 = *(const float4*)(Aptr + (size_t)aRow1 * K + aC0);
    pb0 = *(const float4*)(Bptr + (size_t)bR0 * Nn + bC0);
    pb1 = *(const float4*)(Bptr + (size_t)bR1 * Nn + bC0);

    float acc[4][4][4];
    #pragma unroll
    for (int mt = 0; mt < 4; mt++)
        #pragma unroll
        for (int nt = 0; nt < 4; nt++)
            #pragma unroll
            for (int i = 0; i < 4; i++) acc[mt][nt][i] = 0.f;

    const int nK = K / 16;
    for (int kt = 0; kt < nK; kt++) {
        __syncthreads();
        As[aRow0][aC0 + 0] = f2tf32(pa0.x);
        As[aRow0][aC0 + 1] = f2tf32(pa0.y);
        As[aRow0][aC0 + 2] = f2tf32(pa0.z);
        As[aRow0][aC0 + 3] = f2tf32(pa0.w);
        As[aRow1][aC0 + 0] = f2tf32(pa1.x);
        As[aRow1][aC0 + 1] = f2tf32(pa1.y);
        As[aRow1][aC0 + 2] = f2tf32(pa1.z);
        As[aRow1][aC0 + 3] = f2tf32(pa1.w);
        Bs[bR0][bC0 + 0] = f2tf32(pb0.x);
        Bs[bR0][bC0 + 1] = f2tf32(pb0.y);
        Bs[bR0][bC0 + 2] = f2tf32(pb0.z);
        Bs[bR0][bC0 + 3] = f2tf32(pb0.w);
        Bs[bR1][bC0 + 0] = f2tf32(pb1.x);
        Bs[bR1][bC0 + 1] = f2tf32(pb1.y);
        Bs[bR1][bC0 + 2] = f2tf32(pb1.z);
        Bs[bR1][bC0 + 3] = f2tf32(pb1.w);
        __syncthreads();

        if (kt + 1 < nK) {
            const int k0g = (kt + 1) * 16;
            pa0 = *(const float4*)(Aptr + (size_t)aRow0 * K + k0g + aC0);
            pa1 = *(const float4*)(Aptr + (size_t)aRow1 * K + k0g + aC0);
            pb0 = *(const float4*)(Bptr + (size_t)(k0g + bR0) * Nn + bC0);
            pb1 = *(const float4*)(Bptr + (size_t)(k0g + bR1) * Nn + bC0);
        }

        #pragma unroll
        for (int ks = 0; ks < 2; ks++) {
            const int k0 = ks * 8;
            unsigned af[4][4];
            #pragma unroll
            for (int mt = 0; mt < 4; mt++) {
                const int r = wm * 64 + mt * 16 + g;
                af[mt][0] = As[r    ][k0 + t];
                af[mt][1] = As[r + 8][k0 + t];
                af[mt][2] = As[r    ][k0 + t + 4];
                af[mt][3] = As[r + 8][k0 + t + 4];
            }
            unsigned bf[4][2];
            #pragma unroll
            for (int nt = 0; nt < 4; nt++) {
                const int c = wn * 32 + nt * 8 + g;
                bf[nt][0] = Bs[k0 + t    ][c];
                bf[nt][1] = Bs[k0 + t + 4][c];
            }
            #pragma unroll
            for (int mt = 0; mt < 4; mt++)
                #pragma unroll
                for (int nt = 0; nt < 4; nt++)
                    mma_tf32(acc[mt][nt], af[mt], bf[nt]);
        }
    }

    // epilogue: bias (+gelu), write float2 pairs
    #pragma unroll
    for (int nt = 0; nt < 4; nt++) {
        const int col = n0 + wn * 32 + nt * 8 + 2 * t;
        const float2 bv = *(const float2*)(bias + col);
        #pragma unroll
        for (int mt = 0; mt < 4; mt++) {
            const int row0 = m0 + wm * 64 + mt * 16 + g;
            const int row1 = row0 + 8;
            float2 r0, r1;
            r0.x = acc[mt][nt][0] + bv.x;
            r0.y = acc[mt][nt][1] + bv.y;
            r1.x = acc[mt][nt][2] + bv.x;
            r1.y = acc[mt][nt][3] + bv.y;
            if (DO_GELU) {
                r0.x = 0.5f * r0.x * (1.f + erff(r0.x * 0.70710678118654752f));
                r0.y = 0.5f * r0.y * (1.f + erff(r0.y * 0.70710678118654752f));
                r1.x = 0.5f * r1.x * (1.f + erff(r1.x * 0.70710678118654752f));
                r1.y = 0.5f * r1.y * (1.f + erff(r1.y * 0.70710678118654752f));
            }
            *(float2*)(C + (size_t)row0 * Nn + col) = r0;
            *(float2*)(C + (size_t)row1 * Nn + col) = r1;
        }
    }
}

// ---------------------------------------------------------------------------
// Block-diagonal attention: one CTA per (head, block, batch)
// smem: Qt[64][128] | Kt[64][128] | Vs[128][64] | S[128][129]
// ---------------------------------------------------------------------------
#define ATT_SMEM_FLOATS (8192*3 + 128*129)

__global__ __launch_bounds__(256, 1)
void attn_kernel(const float* __restrict__ Q, const float* __restrict__ K,
                 const float* __restrict__ V, const int* __restrict__ mask,
                 float* __restrict__ O)
{
    extern __shared__ float sm[];
    float* Qt = sm;             // [64][128]
    float* Kt = sm + 8192;      // [64][128]
    float* Vs = sm + 16384;     // [128][64]
    float* S  = sm + 24576;     // [128][129]

    const int h = blockIdx.x, a = blockIdx.y, n = blockIdx.z;
    const int tid = threadIdx.x;
    const int tx = tid & 15, ty = tid >> 4;
    const size_t base = ((size_t)n * LSEQ + (size_t)a * BS) * EMB + h * HDIM;

    #pragma unroll
    for (int i = 0; i < 8; i++) {
        int id = tid + i * 256;
        int r  = id >> 4;        // 0..127
        int d  = (id & 15) * 4;  // 0..60
        float4 q4 = *(const float4*)(Q + base + (size_t)r * EMB + d);
        float4 k4 = *(const float4*)(K + base + (size_t)r * EMB + d);
        float4 v4 = *(const float4*)(V + base + (size_t)r * EMB + d);
        Qt[(d + 0) * 128 + r] = q4.x;
        Qt[(d + 1) * 128 + r] = q4.y;
        Qt[(d + 2) * 128 + r] = q4.z;
        Qt[(d + 3) * 128 + r] = q4.w;
        Kt[(d + 0) * 128 + r] = k4.x;
        Kt[(d + 1) * 128 + r] = k4.y;
        Kt[(d + 2) * 128 + r] = k4.z;
        Kt[(d + 3) * 128 + r] = k4.w;
        *(float4*)&Vs[r * 64 + d] = v4;
    }
    __syncthreads();

    // S = Q @ K^T
    {
        float acc[8][8];
        #pragma unroll
        for (int i = 0; i < 8; i++)
            #pragma unroll
            for (int j = 0; j < 8; j++) acc[i][j] = 0.f;

        #pragma unroll 4
        for (int d = 0; d < 64; d++) {
            float rq[8], rk[8];
            *(float4*)&rq[0] = *(const float4*)&Qt[d * 128 + ty * 8];
            *(float4*)&rq[4] = *(const float4*)&Qt[d * 128 + ty * 8 + 4];
            *(float4*)&rk[0] = *(const float4*)&Kt[d * 128 + tx * 8];
            *(float4*)&rk[4] = *(const float4*)&Kt[d * 128 + tx * 8 + 4];
            #pragma unroll
            for (int i = 0; i < 8; i++)
                #pragma unroll
                for (int j = 0; j < 8; j++)
                    acc[i][j] += rq[i] * rk[j];
        }
        #pragma unroll
        for (int i = 0; i < 8; i++)
            #pragma unroll
            for (int j = 0; j < 8; j++)
                S[(ty * 8 + i) * 129 + tx * 8 + j] = acc[i][j];
    }
    __syncthreads();

    // softmax per row
    {
        const int* mrow = mask + n * (BS * BS);
        const int w = tid >> 5, lane = tid & 31;
        for (int rr = 0; rr < 16; rr++) {
            const int r = w * 16 + rr;
            float x[4];
            #pragma unroll
            for (int j = 0; j < 4; j++) {
                int k = lane + j * 32;
                float s = S[r * 129 + k];
                x[j] = mrow[r * BS + k] ? s * 0.125f : -1e20f;
            }
            float mx = fmaxf(fmaxf(x[0], x[1]), fmaxf(x[2], x[3]));
            #pragma unroll
            for (int off = 16; off >= 1; off >>= 1)
                mx = fmaxf(mx, __shfl_xor_sync(0xffffffffu, mx, off));
            float e[4], sum = 0.f;
            #pragma unroll
            for (int j = 0; j < 4; j++) { e[j] = __expf(x[j] - mx); sum += e[j]; }
            #pragma unroll
            for (int off = 16; off >= 1; off >>= 1)
                sum += __shfl_xor_sync(0xffffffffu, sum, off);
            float inv = 1.f / sum;
            #pragma unroll
            for (int j = 0; j < 4; j++)
                S[r * 129 + lane + j * 32] = e[j] * inv;
        }
    }
    __syncthreads();

    // O = P @ V
    {
        float o[8][4];
        #pragma unroll
        for (int i = 0; i < 8; i++)
            #pragma unroll
            for (int j = 0; j < 4; j++) o[i][j] = 0.f;

        #pragma unroll 2
        for (int k = 0; k < 128; k++) {
            float rv[4];
            *(float4*)&rv[0] = *(const float4*)&Vs[k * 64 + tx * 4];
            float rp[8];
            #pragma unroll
            for (int i = 0; i < 8; i++) rp[i] = S[(ty * 8 + i) * 129 + k];
            #pragma unroll
            for (int i = 0; i < 8; i++)
                #pragma unroll
                for (int j = 0; j < 4; j++)
                    o[i][j] += rp[i] * rv[j];
        }
        #pragma unroll
        for (int i = 0; i < 8; i++) {
            int q = ty * 8 + i;
            float* Op = O + base + (size_t)q * EMB + tx * 4;
            *(float4*)Op = *(float4*)&o[i][0];
        }
    }
}

// ---------------------------------------------------------------------------
// Fused residual-add + LayerNorm: out = LN(A + R) * g + b
// ---------------------------------------------------------------------------
__global__ __launch_bounds__(128)
void ln_kernel(const float* __restrict__ A, const float* __restrict__ R,
               const float* __restrict__ g, const float* __restrict__ b,
               float* __restrict__ out)
{
    __shared__ float red[8];
    const int row = blockIdx.x;
    const int t = threadIdx.x;
    const int lane = t & 31, w = t >> 5;

    float4 x = ((const float4*)(A + (size_t)row * EMB))[t];
    float4 y = ((const float4*)(R + (size_t)row * EMB))[t];
    x.x += y.x; x.y += y.y; x.z += y.z; x.w += y.w;

    float s  = x.x + x.y + x.z + x.w;
    float sq = x.x * x.x + x.y * x.y + x.z * x.z + x.w * x.w;
    #pragma unroll
    for (int off = 16; off >= 1; off >>= 1) {
        s  += __shfl_xor_sync(0xffffffffu, s,  off);
        sq += __shfl_xor_sync(0xffffffffu, sq, off);
    }
    if (lane == 0) { red[w] = s; red[4 + w] = sq; }
    __syncthreads();
    float S  = red[0] + red[1] + red[2] + red[3];
    float SQ = red[4] + red[5] + red[6] + red[7];
    float mean = S * (1.f / EMB);
    float var  = SQ * (1.f / EMB) - mean * mean;
    float rstd = rsqrtf(var + 1e-5f);

    float4 gg = ((const float4*)g)[t];
    float4 bb = ((const float4*)b)[t];
    float4 o;
    o.x = (x.x - mean) * rstd * gg.x + bb.x;
    o.y = (x.y - mean) * rstd * gg.y + bb.y;
    o.z = (x.z - mean) * rstd * gg.z + bb.z;
    o.w = (x.w - mean) * rstd * gg.w + bb.w;
    ((float4*)(out + (size_t)row * EMB))[t] = o;
}

// ---------------------------------------------------------------------------
// Launch
// ---------------------------------------------------------------------------
extern "C" void kernel_launch(void* const* d_in, const int* in_sizes, int n_in,
                              void* d_out, int out_size)
{
    const float* value = (const float*)d_in[0];
    const float* key   = (const float*)d_in[1];
    const float* query = (const float*)d_in[2];
    const int*   mask  = (const int*)  d_in[3];
    const float* wv = (const float*)d_in[4];
    const float* bv = (const float*)d_in[5];
    const float* wk = (const float*)d_in[6];
    const float* bk = (const float*)d_in[7];
    const float* wq = (const float*)d_in[8];
    const float* bq = (const float*)d_in[9];
    const float* wo = (const float*)d_in[10];
    const float* bo = (const float*)d_in[11];
    const float* g1 = (const float*)d_in[12];
    const float* b1 = (const float*)d_in[13];
    const float* w1 = (const float*)d_in[14];
    const float* bf1 = (const float*)d_in[15];
    const float* w2 = (const float*)d_in[16];
    const float* bf2 = (const float*)d_in[17];
    const float* g2 = (const float*)d_in[18];
    const float* b2 = (const float*)d_in[19];
    float* out = (float*)d_out;

    float *gv, *gk, *gq, *gatt, *gtmp, *gx, *gff;
    cudaGetSymbolAddress((void**)&gv,   g_v);
    cudaGetSymbolAddress((void**)&gk,   g_k);
    cudaGetSymbolAddress((void**)&gq,   g_q);
    cudaGetSymbolAddress((void**)&gatt, g_att);
    cudaGetSymbolAddress((void**)&gtmp, g_tmp);
    cudaGetSymbolAddress((void**)&gx,   g_x);
    cudaGetSymbolAddress((void**)&gff,  g_ff);

    cudaFuncSetAttribute(attn_kernel,
                         cudaFuncAttributeMaxDynamicSharedMemorySize,
                         ATT_SMEM_FLOATS * (int)sizeof(float));

    dim3 gProj(EMB / 128, MROWS / 128);   // (4, 256)
    dim3 gFF1 (FFD / 128, MROWS / 128);   // (8, 256)
    dim3 gFF2 (EMB / 128, MROWS / 128);

    // QKV projections (tf32 tensor cores)
    tgemm_bias<0><<<gProj, 256>>>(value, wv, bv, gv, MROWS, EMB, EMB);
    tgemm_bias<0><<<gProj, 256>>>(key,   wk, bk, gk, MROWS, EMB, EMB);
    tgemm_bias<0><<<gProj, 256>>>(query, wq, bq, gq, MROWS, EMB, EMB);

    // block attention
    dim3 gAtt(HEADS, ABLK, NB);
    attn_kernel<<<gAtt, 256, ATT_SMEM_FLOATS * sizeof(float)>>>(gq, gk, gv, mask, gatt);

    // output projection + LN1(out + query)
    tgemm_bias<0><<<gProj, 256>>>(gatt, wo, bo, gtmp, MROWS, EMB, EMB);
    ln_kernel<<<MROWS, 128>>>(gtmp, query, g1, b1, gx);

    // FFN: gelu(x@w1+bf1) @ w2 + bf2 + x, then LN2
    tgemm_bias<1><<<gFF1, 256>>>(gx, w1, bf1, gff, MROWS, FFD, EMB);
    tgemm_bias<0><<<gFF2, 256>>>(gff, w2, bf2, gtmp, MROWS, EMB, FFD);
    ln_kernel<<<MROWS, 128>>>(gtmp, gx, g2, b2, out);
}

// round 3
// speedup vs baseline: 3.3352x; 1.3309x over previous
#include <cuda_runtime.h>
#include <cuda_bf16.h>
#include <cstdint>
#include <cstdio>

// Problem constants
#define NB   4
#define LSEQ 8192
#define EMB  512
#define HEADS 8
#define HDIM 64
#define BS   128
#define ABLK 64          // LSEQ / BS
#define FFD  1024        // 2*EMB
#define MROWS (NB*LSEQ)  // 32768

// ---------------------------------------------------------------------------
// Scratch
// ---------------------------------------------------------------------------
__device__ float g_v  [MROWS * EMB];
__device__ float g_k  [MROWS * EMB];
__device__ float g_q  [MROWS * EMB];
__device__ float g_att[MROWS * EMB];
__device__ float g_tmp[MROWS * EMB];
__device__ float g_x  [MROWS * EMB];
__device__ float g_ff [MROWS * FFD];

// ---------------------------------------------------------------------------
// helpers
// ---------------------------------------------------------------------------
__device__ __forceinline__ void cp16(float* dst, const float* src) {
    unsigned d = (unsigned)__cvta_generic_to_shared(dst);
    asm volatile("cp.async.cg.shared.global [%0], [%1], 16;" :: "r"(d), "l"(src));
}
#define CP_COMMIT() asm volatile("cp.async.commit_group;")
#define CP_WAIT0()  asm volatile("cp.async.wait_group 0;")

__device__ __forceinline__ unsigned fu(float x) { return __float_as_uint(x); }

__device__ __forceinline__ void mma_tf32(float c[4],
                                         const unsigned a[4],
                                         const unsigned b[2]) {
    asm volatile(
        "mma.sync.aligned.m16n8k8.row.col.f32.tf32.tf32.f32 "
        "{%0,%1,%2,%3}, {%4,%5,%6,%7}, {%8,%9}, {%0,%1,%2,%3};"
        : "+f"(c[0]), "+f"(c[1]), "+f"(c[2]), "+f"(c[3])
        : "r"(a[0]), "r"(a[1]), "r"(a[2]), "r"(a[3]),
          "r"(b[0]), "r"(b[1]));
}

// ---------------------------------------------------------------------------
// TF32 GEMM with cp.async double buffering.
// C[M,Nn] = A[M,K] @ B[K,Nn] + bias (+GELU). BM=BN=128, BK=16.
// 256 threads (8 warps 2x4), warp tile 64x32. fp32 bits used directly as
// tf32 operands (hardware truncation).
// ---------------------------------------------------------------------------
template<int DO_GELU>
__global__ __launch_bounds__(256, 2)
void tgemm_bias(const float* __restrict__ A, const float* __restrict__ B,
                const float* __restrict__ bias, float* __restrict__ C,
                int M, int Nn, int K)
{
    __shared__ float As[2][128][20];
    __shared__ float Bs[2][16][136];

    const int tid  = threadIdx.x;
    const int lane = tid & 31;
    const int warp = tid >> 5;
    const int wm   = warp >> 2;
    const int wn   = warp & 3;
    const int g    = lane >> 2;
    const int t    = lane & 3;

    const int m0 = blockIdx.y * 128;
    const int n0 = blockIdx.x * 128;

    const int aRow0 = tid >> 2;          // 0..63
    const int aC0   = (tid & 3) * 4;     // 0,4,8,12
    const int aRow1 = aRow0 + 64;
    const int bR0 = tid >> 5;            // 0..7
    const int bC0 = (tid & 31) * 4;      // 0..124
    const int bR1 = bR0 + 8;

    const float* Aptr = A + (size_t)m0 * K;
    const float* Bptr = B + n0;

    float acc[4][4][4];
    #pragma unroll
    for (int mt = 0; mt < 4; mt++)
        #pragma unroll
        for (int nt = 0; nt < 4; nt++)
            #pragma unroll
            for (int i = 0; i < 4; i++) acc[mt][nt][i] = 0.f;

    const int nK = K / 16;

    // prologue: stage 0
    {
        cp16(&As[0][aRow0][aC0], Aptr + (size_t)aRow0 * K + aC0);
        cp16(&As[0][aRow1][aC0], Aptr + (size_t)aRow1 * K + aC0);
        cp16(&Bs[0][bR0][bC0],   Bptr + (size_t)bR0 * Nn + bC0);
        cp16(&Bs[0][bR1][bC0],   Bptr + (size_t)bR1 * Nn + bC0);
        CP_COMMIT();
    }

    for (int kt = 0; kt < nK; kt++) {
        CP_WAIT0();
        __syncthreads();

        const int s = kt & 1;
        if (kt + 1 < nK) {
            const int k0g = (kt + 1) * 16;
            const int sn = (kt + 1) & 1;
            cp16(&As[sn][aRow0][aC0], Aptr + (size_t)aRow0 * K + k0g + aC0);
            cp16(&As[sn][aRow1][aC0], Aptr + (size_t)aRow1 * K + k0g + aC0);
            cp16(&Bs[sn][bR0][bC0],   Bptr + (size_t)(k0g + bR0) * Nn + bC0);
            cp16(&Bs[sn][bR1][bC0],   Bptr + (size_t)(k0g + bR1) * Nn + bC0);
        }
        CP_COMMIT();

        #pragma unroll
        for (int ks = 0; ks < 2; ks++) {
            const int k0 = ks * 8;
            unsigned af[4][4];
            #pragma unroll
            for (int mt = 0; mt < 4; mt++) {
                const int r = wm * 64 + mt * 16 + g;
                af[mt][0] = fu(As[s][r    ][k0 + t]);
                af[mt][1] = fu(As[s][r + 8][k0 + t]);
                af[mt][2] = fu(As[s][r    ][k0 + t + 4]);
                af[mt][3] = fu(As[s][r + 8][k0 + t + 4]);
            }
            unsigned bf[4][2];
            #pragma unroll
            for (int nt = 0; nt < 4; nt++) {
                const int c = wn * 32 + nt * 8 + g;
                bf[nt][0] = fu(Bs[s][k0 + t    ][c]);
                bf[nt][1] = fu(Bs[s][k0 + t + 4][c]);
            }
            #pragma unroll
            for (int mt = 0; mt < 4; mt++)
                #pragma unroll
                for (int nt = 0; nt < 4; nt++)
                    mma_tf32(acc[mt][nt], af[mt], bf[nt]);
        }
    }

    // epilogue
    #pragma unroll
    for (int nt = 0; nt < 4; nt++) {
        const int col = n0 + wn * 32 + nt * 8 + 2 * t;
        const float2 bv = *(const float2*)(bias + col);
        #pragma unroll
        for (int mt = 0; mt < 4; mt++) {
            const int row0 = m0 + wm * 64 + mt * 16 + g;
            const int row1 = row0 + 8;
            float2 r0, r1;
            r0.x = acc[mt][nt][0] + bv.x;
            r0.y = acc[mt][nt][1] + bv.y;
            r1.x = acc[mt][nt][2] + bv.x;
            r1.y = acc[mt][nt][3] + bv.y;
            if (DO_GELU) {
                r0.x = 0.5f * r0.x * (1.f + erff(r0.x * 0.70710678118654752f));
                r0.y = 0.5f * r0.y * (1.f + erff(r0.y * 0.70710678118654752f));
                r1.x = 0.5f * r1.x * (1.f + erff(r1.x * 0.70710678118654752f));
                r1.y = 0.5f * r1.y * (1.f + erff(r1.y * 0.70710678118654752f));
            }
            *(float2*)(C + (size_t)row0 * Nn + col) = r0;
            *(float2*)(C + (size_t)row1 * Nn + col) = r1;
        }
    }
}

// ---------------------------------------------------------------------------
// Block-diagonal attention with tf32 MMA.
// One CTA per (head, block, batch), 256 threads (8 warps).
// smem floats: Vs[128][72] | Qs[128][68] | Ks[128][68]; S[128][132] overlays Q+K.
// ---------------------------------------------------------------------------
#define AQS 68
#define AVS 72
#define ATT_SMEM_FLOATS (128*AVS + 2*128*AQS)   // 26624 floats = 106,496 B

__global__ __launch_bounds__(256)
void attn_mma(const float* __restrict__ Q, const float* __restrict__ K,
              const float* __restrict__ V, const int* __restrict__ mask,
              float* __restrict__ O)
{
    extern __shared__ float sm[];
    float* Vs = sm;                       // [128][72]
    float* Qs = sm + 128 * AVS;           // [128][68]
    float* Ks = Qs + 128 * AQS;           // [128][68]
    float* S  = Qs;                       // [128][132] overlays Q+K

    const int h = blockIdx.x, a = blockIdx.y, n = blockIdx.z;
    const int tid  = threadIdx.x;
    const int lane = tid & 31;
    const int warp = tid >> 5;
    const int g = lane >> 2;
    const int t = lane & 3;
    const size_t base = ((size_t)n * LSEQ + (size_t)a * BS) * EMB + h * HDIM;

    // async load Q,K,V tiles (128 rows x 64 floats each)
    #pragma unroll
    for (int i = 0; i < 8; i++) {
        int id = tid + i * 256;
        int r  = id >> 4;         // 0..127
        int d4 = (id & 15) * 4;   // 0..60
        const float* src = Q + base + (size_t)r * EMB + d4;
        cp16(&Qs[r * AQS + d4], src);
        cp16(&Ks[r * AQS + d4], K + base + (size_t)r * EMB + d4);
        cp16(&Vs[r * AVS + d4], V + base + (size_t)r * EMB + d4);
    }
    CP_COMMIT();
    CP_WAIT0();
    __syncthreads();

    // ---- S = Q @ K^T (128x128, k=64) ----
    const int wm = warp >> 2;   // 0..1  (64 rows)
    const int wn = warp & 3;    // 0..3  (32 cols)
    float acc[4][4][4];
    #pragma unroll
    for (int mt = 0; mt < 4; mt++)
        #pragma unroll
        for (int nt = 0; nt < 4; nt++)
            #pragma unroll
            for (int i = 0; i < 4; i++) acc[mt][nt][i] = 0.f;

    #pragma unroll
    for (int ks = 0; ks < 8; ks++) {
        const int k0 = ks * 8;
        unsigned af[4][4];
        #pragma unroll
        for (int mt = 0; mt < 4; mt++) {
            const int r = wm * 64 + mt * 16 + g;
            af[mt][0] = fu(Qs[(r    ) * AQS + k0 + t]);
            af[mt][1] = fu(Qs[(r + 8) * AQS + k0 + t]);
            af[mt][2] = fu(Qs[(r    ) * AQS + k0 + t + 4]);
            af[mt][3] = fu(Qs[(r + 8) * AQS + k0 + t + 4]);
        }
        unsigned bf[4][2];
        #pragma unroll
        for (int nt = 0; nt < 4; nt++) {
            const int c = wn * 32 + nt * 8 + g;
            bf[nt][0] = fu(Ks[c * AQS + k0 + t]);
            bf[nt][1] = fu(Ks[c * AQS + k0 + t + 4]);
        }
        #pragma unroll
        for (int mt = 0; mt < 4; mt++)
            #pragma unroll
            for (int nt = 0; nt < 4; nt++)
                mma_tf32(acc[mt][nt], af[mt], bf[nt]);
    }
    __syncthreads();   // all Q/K reads done; S may overwrite

    #pragma unroll
    for (int mt = 0; mt < 4; mt++) {
        const int r = wm * 64 + mt * 16 + g;
        #pragma unroll
        for (int nt = 0; nt < 4; nt++) {
            const int col = wn * 32 + nt * 8 + 2 * t;
            float2 lo = { acc[mt][nt][0], acc[mt][nt][1] };
            float2 hi = { acc[mt][nt][2], acc[mt][nt][3] };
            *(float2*)&S[(r    ) * 132 + col] = lo;
            *(float2*)&S[(r + 8) * 132 + col] = hi;
        }
    }
    __syncthreads();

    // ---- softmax rows (8 warps x 16 rows), mask + 1/sqrt(64) ----
    {
        const int* mrow = mask + n * (BS * BS);
        for (int rr = 0; rr < 16; rr++) {
            const int r = warp * 16 + rr;
            float x[4];
            #pragma unroll
            for (int j = 0; j < 4; j++) {
                int k = lane + j * 32;
                float s = S[r * 132 + k];
                x[j] = mrow[r * BS + k] ? s * 0.125f : -1e20f;
            }
            float mx = fmaxf(fmaxf(x[0], x[1]), fmaxf(x[2], x[3]));
            #pragma unroll
            for (int off = 16; off >= 1; off >>= 1)
                mx = fmaxf(mx, __shfl_xor_sync(0xffffffffu, mx, off));
            float e[4], sum = 0.f;
            #pragma unroll
            for (int j = 0; j < 4; j++) { e[j] = __expf(x[j] - mx); sum += e[j]; }
            #pragma unroll
            for (int off = 16; off >= 1; off >>= 1)
                sum += __shfl_xor_sync(0xffffffffu, sum, off);
            float inv = 1.f / sum;
            #pragma unroll
            for (int j = 0; j < 4; j++)
                S[r * 132 + lane + j * 32] = e[j] * inv;
        }
    }
    __syncthreads();

    // ---- O = P @ V (128x64, k=128) ----
    const int wm2 = warp >> 1;  // 0..3 (32 rows)
    const int wn2 = warp & 1;   // 0..1 (32 cols)
    float o[2][4][4];
    #pragma unroll
    for (int mt = 0; mt < 2; mt++)
        #pragma unroll
        for (int nt = 0; nt < 4; nt++)
            #pragma unroll
            for (int i = 0; i < 4; i++) o[mt][nt][i] = 0.f;

    #pragma unroll
    for (int ks = 0; ks < 16; ks++) {
        const int k0 = ks * 8;
        unsigned af[2][4];
        #pragma unroll
        for (int mt = 0; mt < 2; mt++) {
            const int r = wm2 * 32 + mt * 16 + g;
            af[mt][0] = fu(S[(r    ) * 132 + k0 + t]);
            af[mt][1] = fu(S[(r + 8) * 132 + k0 + t]);
            af[mt][2] = fu(S[(r    ) * 132 + k0 + t + 4]);
            af[mt][3] = fu(S[(r + 8) * 132 + k0 + t + 4]);
        }
        unsigned bf[4][2];
        #pragma unroll
        for (int nt = 0; nt < 4; nt++) {
            const int c = wn2 * 32 + nt * 8 + g;
            bf[nt][0] = fu(Vs[(k0 + t    ) * AVS + c]);
            bf[nt][1] = fu(Vs[(k0 + t + 4) * AVS + c]);
        }
        #pragma unroll
        for (int mt = 0; mt < 2; mt++)
            #pragma unroll
            for (int nt = 0; nt < 4; nt++)
                mma_tf32(o[mt][nt], af[mt], bf[nt]);
    }

    #pragma unroll
    for (int mt = 0; mt < 2; mt++) {
        const int r = wm2 * 32 + mt * 16 + g;
        #pragma unroll
        for (int nt = 0; nt < 4; nt++) {
            const int col = wn2 * 32 + nt * 8 + 2 * t;
            float2 lo = { o[mt][nt][0], o[mt][nt][1] };
            float2 hi = { o[mt][nt][2], o[mt][nt][3] };
            *(float2*)(O + base + (size_t)(r    ) * EMB + col) = lo;
            *(float2*)(O + base + (size_t)(r + 8) * EMB + col) = hi;
        }
    }
}

// ---------------------------------------------------------------------------
// Fused residual-add + LayerNorm: out = LN(A + R) * g + b
// ---------------------------------------------------------------------------
__global__ __launch_bounds__(128)
void ln_kernel(const float* __restrict__ A, const float* __restrict__ R,
               const float* __restrict__ g, const float* __restrict__ b,
               float* __restrict__ out)
{
    __shared__ float red[8];
    const int row = blockIdx.x;
    const int t = threadIdx.x;
    const int lane = t & 31, w = t >> 5;

    float4 x = ((const float4*)(A + (size_t)row * EMB))[t];
    float4 y = ((const float4*)(R + (size_t)row * EMB))[t];
    x.x += y.x; x.y += y.y; x.z += y.z; x.w += y.w;

    float s  = x.x + x.y + x.z + x.w;
    float sq = x.x * x.x + x.y * x.y + x.z * x.z + x.w * x.w;
    #pragma unroll
    for (int off = 16; off >= 1; off >>= 1) {
        s  += __shfl_xor_sync(0xffffffffu, s,  off);
        sq += __shfl_xor_sync(0xffffffffu, sq, off);
    }
    if (lane == 0) { red[w] = s; red[4 + w] = sq; }
    __syncthreads();
    float S  = red[0] + red[1] + red[2] + red[3];
    float SQ = red[4] + red[5] + red[6] + red[7];
    float mean = S * (1.f / EMB);
    float var  = SQ * (1.f / EMB) - mean * mean;
    float rstd = rsqrtf(var + 1e-5f);

    float4 gg = ((const float4*)g)[t];
    float4 bb = ((const float4*)b)[t];
    float4 o;
    o.x = (x.x - mean) * rstd * gg.x + bb.x;
    o.y = (x.y - mean) * rstd * gg.y + bb.y;
    o.z = (x.z - mean) * rstd * gg.z + bb.z;
    o.w = (x.w - mean) * rstd * gg.w + bb.w;
    ((float4*)(out + (size_t)row * EMB))[t] = o;
}

// ---------------------------------------------------------------------------
// Launch
// ---------------------------------------------------------------------------
extern "C" void kernel_launch(void* const* d_in, const int* in_sizes, int n_in,
                              void* d_out, int out_size)
{
    const float* value = (const float*)d_in[0];
    const float* key   = (const float*)d_in[1];
    const float* query = (const float*)d_in[2];
    const int*   mask  = (const int*)  d_in[3];
    const float* wv = (const float*)d_in[4];
    const float* bv = (const float*)d_in[5];
    const float* wk = (const float*)d_in[6];
    const float* bk = (const float*)d_in[7];
    const float* wq = (const float*)d_in[8];
    const float* bq = (const float*)d_in[9];
    const float* wo = (const float*)d_in[10];
    const float* bo = (const float*)d_in[11];
    const float* g1 = (const float*)d_in[12];
    const float* b1 = (const float*)d_in[13];
    const float* w1 = (const float*)d_in[14];
    const float* bf1 = (const float*)d_in[15];
    const float* w2 = (const float*)d_in[16];
    const float* bf2 = (const float*)d_in[17];
    const float* g2 = (const float*)d_in[18];
    const float* b2 = (const float*)d_in[19];
    float* out = (float*)d_out;

    float *gv, *gk, *gq, *gatt, *gtmp, *gx, *gff;
    cudaGetSymbolAddress((void**)&gv,   g_v);
    cudaGetSymbolAddress((void**)&gk,   g_k);
    cudaGetSymbolAddress((void**)&gq,   g_q);
    cudaGetSymbolAddress((void**)&gatt, g_att);
    cudaGetSymbolAddress((void**)&gtmp, g_tmp);
    cudaGetSymbolAddress((void**)&gx,   g_x);
    cudaGetSymbolAddress((void**)&gff,  g_ff);

    cudaFuncSetAttribute(attn_mma,
                         cudaFuncAttributeMaxDynamicSharedMemorySize,
                         ATT_SMEM_FLOATS * (int)sizeof(float));

    dim3 gProj(EMB / 128, MROWS / 128);   // (4, 256)
    dim3 gFF1 (FFD / 128, MROWS / 128);   // (8, 256)
    dim3 gFF2 (EMB / 128, MROWS / 128);

    // QKV projections
    tgemm_bias<0><<<gProj, 256>>>(value, wv, bv, gv, MROWS, EMB, EMB);
    tgemm_bias<0><<<gProj, 256>>>(key,   wk, bk, gk, MROWS, EMB, EMB);
    tgemm_bias<0><<<gProj, 256>>>(query, wq, bq, gq, MROWS, EMB, EMB);

    // block attention (tensor cores)
    dim3 gAtt(HEADS, ABLK, NB);
    attn_mma<<<gAtt, 256, ATT_SMEM_FLOATS * sizeof(float)>>>(gq, gk, gv, mask, gatt);

    // output projection + LN1(out + query)
    tgemm_bias<0><<<gProj, 256>>>(gatt, wo, bo, gtmp, MROWS, EMB, EMB);
    ln_kernel<<<MROWS, 128>>>(gtmp, query, g1, b1, gx);

    // FFN: gelu(x@w1+bf1) @ w2 + bf2 + x, then LN2
    tgemm_bias<1><<<gFF1, 256>>>(gx, w1, bf1, gff, MROWS, FFD, EMB);
    tgemm_bias<0><<<gFF2, 256>>>(gff, w2, bf2, gtmp, MROWS, EMB, FFD);
    ln_kernel<<<MROWS, 128>>>(gtmp, gx, g2, b2, out);
}

// round 5
// speedup vs baseline: 6.4761x; 1.9417x over previous
#include <cuda_runtime.h>
#include <cuda_fp16.h>
#include <cstdint>
#include <cstdio>

// Problem constants
#define NB   4
#define LSEQ 8192
#define EMB  512
#define HEADS 8
#define HDIM 64
#define BS   128
#define ABLK 64
#define FFD  1024
#define MROWS (NB*LSEQ)  // 32768

// ---------------------------------------------------------------------------
// Scratch
// ---------------------------------------------------------------------------
__device__ __half h_val[MROWS * EMB];
__device__ __half h_key[MROWS * EMB];
__device__ __half h_qry[MROWS * EMB];
__device__ __half h_q  [MROWS * EMB];
__device__ __half h_k  [MROWS * EMB];
__device__ __half h_v  [MROWS * EMB];
__device__ __half h_att[MROWS * EMB];
__device__ __half h_x  [MROWS * EMB];
__device__ __half h_ff [MROWS * FFD];
__device__ float  g_tmp[MROWS * EMB];
__device__ float  g_x  [MROWS * EMB];
// fp16 transposed weights (K-major [N][K])
__device__ __half g_wvt[EMB * EMB];
__device__ __half g_wkt[EMB * EMB];
__device__ __half g_wqt[EMB * EMB];
__device__ __half g_wot[EMB * EMB];
__device__ __half g_w1t[FFD * EMB];
__device__ __half g_w2t[EMB * FFD];

// ---------------------------------------------------------------------------
// helpers
// ---------------------------------------------------------------------------
__device__ __forceinline__ void cp16s(unsigned saddr, const void* src) {
    asm volatile("cp.async.cg.shared.global [%0], [%1], 16;" :: "r"(saddr), "l"(src));
}
#define CP_COMMIT() asm volatile("cp.async.commit_group;")
#define CP_WAIT0()  asm volatile("cp.async.wait_group 0;")
#define CP_WAIT1()  asm volatile("cp.async.wait_group 1;")

__device__ __forceinline__ unsigned smem_u32(const void* p) {
    return (unsigned)__cvta_generic_to_shared(p);
}

__device__ __forceinline__ void ldm_x4(uint32_t r[4], unsigned addr) {
    asm volatile("ldmatrix.sync.aligned.m8n8.x4.shared.b16 {%0,%1,%2,%3}, [%4];"
                 : "=r"(r[0]), "=r"(r[1]), "=r"(r[2]), "=r"(r[3]) : "r"(addr));
}
__device__ __forceinline__ void ldm_x4t(uint32_t r[4], unsigned addr) {
    asm volatile("ldmatrix.sync.aligned.m8n8.x4.trans.shared.b16 {%0,%1,%2,%3}, [%4];"
                 : "=r"(r[0]), "=r"(r[1]), "=r"(r[2]), "=r"(r[3]) : "r"(addr));
}

__device__ __forceinline__ void mma_f16(float c[4], const uint32_t a[4],
                                        const uint32_t b[2]) {
    asm volatile(
        "mma.sync.aligned.m16n8k16.row.col.f32.f16.f16.f32 "
        "{%0,%1,%2,%3}, {%4,%5,%6,%7}, {%8,%9}, {%0,%1,%2,%3};"
        : "+f"(c[0]), "+f"(c[1]), "+f"(c[2]), "+f"(c[3])
        : "r"(a[0]), "r"(a[1]), "r"(a[2]), "r"(a[3]), "r"(b[0]), "r"(b[1]));
}

__device__ __forceinline__ uint32_t pack2(float x, float y) {
    __half2 h = __floats2half2_rn(x, y);
    return *(uint32_t*)&h;
}

// ---------------------------------------------------------------------------
// FP16 tensor-core GEMM: C[M,Nn] = A[M,K] @ Bt[Nn,K]^T + bias (+GELU)
// A, Bt fp16 (K-major). CTA 128x128, BK=64 halves (128B rows, SW128),
// 2-stage cp.async, 8 warps 2x4, warp tile 64x32, ldmatrix fragments.
// ---------------------------------------------------------------------------
#define HG_SMEM (2 * 32768)

template<int OUT_HALF, int DO_GELU>
__global__ __launch_bounds__(256, 2)
void hgemm(const __half* __restrict__ A, const __half* __restrict__ Bt,
           const float* __restrict__ bias, void* __restrict__ Cout,
           int M, int Nn, int K)
{
    extern __shared__ __align__(1024) char smem[];
    const unsigned sb = smem_u32(smem);

    const int tid  = threadIdx.x;
    const int lane = tid & 31;
    const int warp = tid >> 5;
    const int wm   = warp >> 2;       // 0..1
    const int wn   = warp & 3;        // 0..3
    const int g    = lane >> 2;
    const int t    = lane & 3;

    const int m0 = blockIdx.y * 128;
    const int n0 = blockIdx.x * 128;
    const __half* Ag = A  + (size_t)m0 * K;
    const __half* Bg = Bt + (size_t)n0 * K;

    // per-lane ldmatrix base rows
    const unsigned rA = (unsigned)(wm * 64 + (lane & 7) + ((lane >> 3) & 1) * 8);
    const unsigned kgA0 = (unsigned)(lane >> 4);
    const unsigned rB = (unsigned)(wn * 32 + (lane & 7) + ((lane >> 4) & 1) * 8);
    const unsigned kgB0 = (unsigned)((lane >> 3) & 1);

    float acc[4][4][4];
    #pragma unroll
    for (int mt = 0; mt < 4; mt++)
        #pragma unroll
        for (int nt = 0; nt < 4; nt++)
            #pragma unroll
            for (int i = 0; i < 4; i++) acc[mt][nt][i] = 0.f;

    const int nCh = K / 64;

    auto load_chunk = [&](int s, int kc) {
        const unsigned sA = sb + s * 32768;
        const unsigned sB = sA + 16384;
        const __half* Ac = Ag + kc * 64;
        const __half* Bc = Bg + kc * 64;
        #pragma unroll
        for (int i = 0; i < 4; i++) {
            int id = tid + i * 256;          // 0..1023
            int r  = id >> 3;                // 0..127
            int kg = id & 7;
            unsigned off = (unsigned)(r * 128 + kg * 16);
            unsigned sw  = off ^ ((off >> 3) & 0x70);
            cp16s(sA + sw, Ac + (size_t)r * K + kg * 8);
            cp16s(sB + sw, Bc + (size_t)r * K + kg * 8);
        }
    };

    load_chunk(0, 0); CP_COMMIT();
    load_chunk(1, 1); CP_COMMIT();

    for (int c = 0; c < nCh; c++) {
        CP_WAIT1();
        __syncthreads();
        const int s = c & 1;
        const unsigned sA = sb + s * 32768;
        const unsigned sB = sA + 16384;

        #pragma unroll
        for (int ks = 0; ks < 4; ks++) {
            uint32_t a[4][4];
            #pragma unroll
            for (int mt = 0; mt < 4; mt++) {
                unsigned addr = sA + (((rA + mt * 16) << 7))
                              + ((((kgA0 + 2 * ks) ^ (rA & 7))) << 4);
                ldm_x4(a[mt], addr);
            }
            uint32_t b[4][2];
            #pragma unroll
            for (int p = 0; p < 2; p++) {
                uint32_t r4[4];
                unsigned addr = sB + (((rB + p * 16) << 7))
                              + ((((kgB0 + 2 * ks) ^ (rB & 7))) << 4);
                ldm_x4(r4, addr);
                b[2*p][0] = r4[0]; b[2*p][1] = r4[1];
                b[2*p+1][0] = r4[2]; b[2*p+1][1] = r4[3];
            }
            #pragma unroll
            for (int mt = 0; mt < 4; mt++)
                #pragma unroll
                for (int nt = 0; nt < 4; nt++)
                    mma_f16(acc[mt][nt], a[mt], b[nt]);
        }

        __syncthreads();
        if (c + 2 < nCh) load_chunk(s, c + 2);
        CP_COMMIT();
    }

    // epilogue
    #pragma unroll
    for (int nt = 0; nt < 4; nt++) {
        const int col = n0 + wn * 32 + nt * 8 + 2 * t;
        const float2 bv = *(const float2*)(bias + col);
        #pragma unroll
        for (int mt = 0; mt < 4; mt++) {
            const int row0 = m0 + wm * 64 + mt * 16 + g;
            const int row1 = row0 + 8;
            float v0 = acc[mt][nt][0] + bv.x;
            float v1 = acc[mt][nt][1] + bv.y;
            float v2 = acc[mt][nt][2] + bv.x;
            float v3 = acc[mt][nt][3] + bv.y;
            if (DO_GELU) {
                v0 = 0.5f * v0 * (1.f + erff(v0 * 0.70710678118654752f));
                v1 = 0.5f * v1 * (1.f + erff(v1 * 0.70710678118654752f));
                v2 = 0.5f * v2 * (1.f + erff(v2 * 0.70710678118654752f));
                v3 = 0.5f * v3 * (1.f + erff(v3 * 0.70710678118654752f));
            }
            if (OUT_HALF) {
                __half* C = (__half*)Cout;
                *(uint32_t*)(C + (size_t)row0 * Nn + col) = pack2(v0, v1);
                *(uint32_t*)(C + (size_t)row1 * Nn + col) = pack2(v2, v3);
            } else {
                float* C = (float*)Cout;
                *(float2*)(C + (size_t)row0 * Nn + col) = make_float2(v0, v1);
                *(float2*)(C + (size_t)row1 * Nn + col) = make_float2(v2, v3);
            }
        }
    }
}

// ---------------------------------------------------------------------------
// FP16 block-diagonal attention, FA-style (no S smem; softmax in registers).
// One CTA per (head, block, batch), 256 threads (8 warps x 16 rows).
// smem: Qh | Kh | Vh, each 128x64 halves (SW128). 48KB.
// ---------------------------------------------------------------------------
#define ATT_SMEM (3 * 16384)

__global__ __launch_bounds__(256)
void attn_h(const __half* __restrict__ Q, const __half* __restrict__ K,
            const __half* __restrict__ V, const int* __restrict__ mask,
            __half* __restrict__ O)
{
    extern __shared__ __align__(1024) char smem[];
    const unsigned sQ = smem_u32(smem);
    const unsigned sK = sQ + 16384;
    const unsigned sV = sK + 16384;

    const int h = blockIdx.x, a = blockIdx.y, n = blockIdx.z;
    const int tid  = threadIdx.x;
    const int lane = tid & 31;
    const int w    = tid >> 5;
    const int g    = lane >> 2;
    const int t    = lane & 3;
    const size_t base = ((size_t)n * LSEQ + (size_t)a * BS) * EMB + h * HDIM;

    // load Q,K,V tiles: 128 rows x 64 halves each = 1024 granules per tile
    #pragma unroll
    for (int i = 0; i < 4; i++) {
        int id = tid + i * 256;
        int r  = id >> 3;
        int kg = id & 7;
        unsigned off = (unsigned)(r * 128 + kg * 16);
        unsigned sw  = off ^ ((off >> 3) & 0x70);
        const size_t go = base + (size_t)r * EMB + kg * 8;
        cp16s(sQ + sw, Q + go);
        cp16s(sK + sw, K + go);
        cp16s(sV + sw, V + go);
    }
    CP_COMMIT();
    CP_WAIT0();
    __syncthreads();

    // ---- S = Q @ K^T : warp w covers rows 16w..16w+15, all 128 cols ----
    float accs[16][4];
    #pragma unroll
    for (int nt = 0; nt < 16; nt++)
        #pragma unroll
        for (int i = 0; i < 4; i++) accs[nt][i] = 0.f;

    const unsigned rQ = (unsigned)(w * 16 + (lane & 7) + ((lane >> 3) & 1) * 8);
    const unsigned kgQ0 = (unsigned)(lane >> 4);
    const unsigned rK0 = (unsigned)((lane & 7) + ((lane >> 4) & 1) * 8);
    const unsigned kgK0 = (unsigned)((lane >> 3) & 1);

    #pragma unroll
    for (int ks = 0; ks < 4; ks++) {
        uint32_t aq[4];
        {
            unsigned addr = sQ + (rQ << 7) + ((((kgQ0 + 2 * ks) ^ (rQ & 7))) << 4);
            ldm_x4(aq, addr);
        }
        #pragma unroll
        for (int p = 0; p < 8; p++) {
            uint32_t r4[4];
            unsigned rKp = rK0 + p * 16;
            unsigned addr = sK + (rKp << 7) + ((((kgK0 + 2 * ks) ^ (rKp & 7))) << 4);
            ldm_x4(r4, addr);
            uint32_t b0[2] = { r4[0], r4[1] };
            uint32_t b1[2] = { r4[2], r4[3] };
            mma_f16(accs[2*p],   aq, b0);
            mma_f16(accs[2*p+1], aq, b1);
        }
    }

    // ---- mask + scale; row max/sum via quad shuffles ----
    const int* mrow = mask + n * (BS * BS);
    const int r0 = w * 16 + g;
    const int r1 = r0 + 8;
    float mx0 = -1e30f, mx1 = -1e30f;
    #pragma unroll
    for (int nt = 0; nt < 16; nt++) {
        const int c = 2 * t + 8 * nt;
        int2 m0v = *(const int2*)(mrow + (size_t)r0 * BS + c);
        int2 m1v = *(const int2*)(mrow + (size_t)r1 * BS + c);
        accs[nt][0] = m0v.x ? accs[nt][0] * 0.125f : -1e20f;
        accs[nt][1] = m0v.y ? accs[nt][1] * 0.125f : -1e20f;
        accs[nt][2] = m1v.x ? accs[nt][2] * 0.125f : -1e20f;
        accs[nt][3] = m1v.y ? accs[nt][3] * 0.125f : -1e20f;
        mx0 = fmaxf(mx0, fmaxf(accs[nt][0], accs[nt][1]));
        mx1 = fmaxf(mx1, fmaxf(accs[nt][2], accs[nt][3]));
    }
    #pragma unroll
    for (int off = 1; off <= 2; off <<= 1) {
        mx0 = fmaxf(mx0, __shfl_xor_sync(0xffffffffu, mx0, off));
        mx1 = fmaxf(mx1, __shfl_xor_sync(0xffffffffu, mx1, off));
    }
    float sum0 = 0.f, sum1 = 0.f;
    #pragma unroll
    for (int nt = 0; nt < 16; nt++) {
        accs[nt][0] = __expf(accs[nt][0] - mx0);
        accs[nt][1] = __expf(accs[nt][1] - mx0);
        accs[nt][2] = __expf(accs[nt][2] - mx1);
        accs[nt][3] = __expf(accs[nt][3] - mx1);
        sum0 += accs[nt][0] + accs[nt][1];
        sum1 += accs[nt][2] + accs[nt][3];
    }
    #pragma unroll
    for (int off = 1; off <= 2; off <<= 1) {
        sum0 += __shfl_xor_sync(0xffffffffu, sum0, off);
        sum1 += __shfl_xor_sync(0xffffffffu, sum1, off);
    }
    const float inv0 = 1.f / sum0;
    const float inv1 = 1.f / sum1;

    // ---- O = P @ V : P fragments packed in-register ----
    float o[8][4];
    #pragma unroll
    for (int nt = 0; nt < 8; nt++)
        #pragma unroll
        for (int i = 0; i < 4; i++) o[nt][i] = 0.f;

    const unsigned rV0 = (unsigned)((lane & 7) + ((lane >> 3) & 1) * 8);
    const unsigned kgV0 = (unsigned)(lane >> 4);

    #pragma unroll
    for (int ks = 0; ks < 8; ks++) {
        uint32_t ap[4];
        ap[0] = pack2(accs[2*ks][0],   accs[2*ks][1]);
        ap[1] = pack2(accs[2*ks][2],   accs[2*ks][3]);
        ap[2] = pack2(accs[2*ks+1][0], accs[2*ks+1][1]);
        ap[3] = pack2(accs[2*ks+1][2], accs[2*ks+1][3]);
        #pragma unroll
        for (int p = 0; p < 4; p++) {
            uint32_t r4[4];
            unsigned rv = rV0 + ks * 16;
            unsigned addr = sV + (rv << 7) + ((((kgV0 + 2 * p) ^ (rv & 7))) << 4);
            ldm_x4t(r4, addr);
            uint32_t b0[2] = { r4[0], r4[1] };
            uint32_t b1[2] = { r4[2], r4[3] };
            mma_f16(o[2*p],   ap, b0);
            mma_f16(o[2*p+1], ap, b1);
        }
    }

    // scale + store
    #pragma unroll
    for (int nt = 0; nt < 8; nt++) {
        const int d = 2 * t + 8 * nt;
        *(uint32_t*)(O + base + (size_t)r0 * EMB + d) =
            pack2(o[nt][0] * inv0, o[nt][1] * inv0);
        *(uint32_t*)(O + base + (size_t)r1 * EMB + d) =
            pack2(o[nt][2] * inv1, o[nt][3] * inv1);
    }
}

// ---------------------------------------------------------------------------
// transpose weight fp32 [K][N] -> fp16 K-major [N][K]
// ---------------------------------------------------------------------------
__global__ __launch_bounds__(256)
void transpose_h(const float* __restrict__ in, __half* __restrict__ out,
                 int K, int N)
{
    __shared__ float tb[32][33];
    const int kb = blockIdx.x * 32, nb = blockIdx.y * 32;
    const int x = threadIdx.x & 31, y = (threadIdx.x >> 5) * 4;
    #pragma unroll
    for (int i = 0; i < 4; i++)
        tb[y + i][x] = in[(size_t)(kb + y + i) * N + nb + x];
    __syncthreads();
    #pragma unroll
    for (int i = 0; i < 4; i++)
        out[(size_t)(nb + y + i) * K + kb + x] = __float2half(tb[x][y + i]);
}

// ---------------------------------------------------------------------------
// convert 3 fp32 tensors to fp16
// ---------------------------------------------------------------------------
__global__ __launch_bounds__(256)
void cvt3(const float* __restrict__ a, const float* __restrict__ b,
          const float* __restrict__ c, __half* __restrict__ ha,
          __half* __restrict__ hb, __half* __restrict__ hc, int n4)
{
    int i = blockIdx.x * blockDim.x + threadIdx.x;
    if (i >= n4) return;
    float4 x;
    uint2 u;
    x = ((const float4*)a)[i];
    u.x = pack2(x.x, x.y); u.y = pack2(x.z, x.w);
    ((uint2*)ha)[i] = u;
    x = ((const float4*)b)[i];
    u.x = pack2(x.x, x.y); u.y = pack2(x.z, x.w);
    ((uint2*)hb)[i] = u;
    x = ((const float4*)c)[i];
    u.x = pack2(x.x, x.y); u.y = pack2(x.z, x.w);
    ((uint2*)hc)[i] = u;
}

// ---------------------------------------------------------------------------
// Fused residual-add + LayerNorm; optional fp16 copy of output
// ---------------------------------------------------------------------------
template<int DUAL>
__global__ __launch_bounds__(128)
void ln_kernel(const float* __restrict__ A, const float* __restrict__ R,
               const float* __restrict__ g, const float* __restrict__ b,
               float* __restrict__ out, __half* __restrict__ hout)
{
    __shared__ float red[8];
    const int row = blockIdx.x;
    const int t = threadIdx.x;
    const int lane = t & 31, w = t >> 5;

    float4 x = ((const float4*)(A + (size_t)row * EMB))[t];
    float4 y = ((const float4*)(R + (size_t)row * EMB))[t];
    x.x += y.x; x.y += y.y; x.z += y.z; x.w += y.w;

    float s  = x.x + x.y + x.z + x.w;
    float sq = x.x * x.x + x.y * x.y + x.z * x.z + x.w * x.w;
    #pragma unroll
    for (int off = 16; off >= 1; off >>= 1) {
        s  += __shfl_xor_sync(0xffffffffu, s,  off);
        sq += __shfl_xor_sync(0xffffffffu, sq, off);
    }
    if (lane == 0) { red[w] = s; red[4 + w] = sq; }
    __syncthreads();
    float S  = red[0] + red[1] + red[2] + red[3];
    float SQ = red[4] + red[5] + red[6] + red[7];
    float mean = S * (1.f / EMB);
    float var  = SQ * (1.f / EMB) - mean * mean;
    float rstd = rsqrtf(var + 1e-5f);

    float4 gg = ((const float4*)g)[t];
    float4 bb = ((const float4*)b)[t];
    float4 o;
    o.x = (x.x - mean) * rstd * gg.x + bb.x;
    o.y = (x.y - mean) * rstd * gg.y + bb.y;
    o.z = (x.z - mean) * rstd * gg.z + bb.z;
    o.w = (x.w - mean) * rstd * gg.w + bb.w;
    ((float4*)(out + (size_t)row * EMB))[t] = o;
    if (DUAL) {
        uint2 u;
        u.x = pack2(o.x, o.y); u.y = pack2(o.z, o.w);
        ((uint2*)(hout + (size_t)row * EMB))[t] = u;
    }
}

// ---------------------------------------------------------------------------
// Launch
// ---------------------------------------------------------------------------
extern "C" void kernel_launch(void* const* d_in, const int* in_sizes, int n_in,
                              void* d_out, int out_size)
{
    const float* value = (const float*)d_in[0];
    const float* key   = (const float*)d_in[1];
    const float* query = (const float*)d_in[2];
    const int*   mask  = (const int*)  d_in[3];
    const float* wv = (const float*)d_in[4];
    const float* bv = (const float*)d_in[5];
    const float* wk = (const float*)d_in[6];
    const float* bk = (const float*)d_in[7];
    const float* wq = (const float*)d_in[8];
    const float* bq = (const float*)d_in[9];
    const float* wo = (const float*)d_in[10];
    const float* bo = (const float*)d_in[11];
    const float* g1 = (const float*)d_in[12];
    const float* b1 = (const float*)d_in[13];
    const float* w1 = (const float*)d_in[14];
    const float* bf1 = (const float*)d_in[15];
    const float* w2 = (const float*)d_in[16];
    const float* bf2 = (const float*)d_in[17];
    const float* g2 = (const float*)d_in[18];
    const float* b2 = (const float*)d_in[19];
    float* out = (float*)d_out;

    __half *hval, *hkey, *hqry, *hq, *hk, *hv, *hatt, *hx, *hff;
    __half *wvt, *wkt, *wqt, *wot, *w1t, *w2t;
    float *gtmp, *gx;
    cudaGetSymbolAddress((void**)&hval, h_val);
    cudaGetSymbolAddress((void**)&hkey, h_key);
    cudaGetSymbolAddress((void**)&hqry, h_qry);
    cudaGetSymbolAddress((void**)&hq,   h_q);
    cudaGetSymbolAddress((void**)&hk,   h_k);
    cudaGetSymbolAddress((void**)&hv,   h_v);
    cudaGetSymbolAddress((void**)&hatt, h_att);
    cudaGetSymbolAddress((void**)&hx,   h_x);
    cudaGetSymbolAddress((void**)&hff,  h_ff);
    cudaGetSymbolAddress((void**)&wvt,  g_wvt);
    cudaGetSymbolAddress((void**)&wkt,  g_wkt);
    cudaGetSymbolAddress((void**)&wqt,  g_wqt);
    cudaGetSymbolAddress((void**)&wot,  g_wot);
    cudaGetSymbolAddress((void**)&w1t,  g_w1t);
    cudaGetSymbolAddress((void**)&w2t,  g_w2t);
    cudaGetSymbolAddress((void**)&gtmp, g_tmp);
    cudaGetSymbolAddress((void**)&gx,   g_x);

    cudaFuncSetAttribute(hgemm<1,0>,
        cudaFuncAttributeMaxDynamicSharedMemorySize, HG_SMEM);
    cudaFuncSetAttribute(hgemm<0,0>,
        cudaFuncAttributeMaxDynamicSharedMemorySize, HG_SMEM);
    cudaFuncSetAttribute(hgemm<1,1>,
        cudaFuncAttributeMaxDynamicSharedMemorySize, HG_SMEM);
    cudaFuncSetAttribute(attn_h,
        cudaFuncAttributeMaxDynamicSharedMemorySize, ATT_SMEM);

    // weight transposes (fp16 K-major) + input conversion
    transpose_h<<<dim3(EMB/32, EMB/32), 256>>>(wv, wvt, EMB, EMB);
    transpose_h<<<dim3(EMB/32, EMB/32), 256>>>(wk, wkt, EMB, EMB);
    transpose_h<<<dim3(EMB/32, EMB/32), 256>>>(wq, wqt, EMB, EMB);
    transpose_h<<<dim3(EMB/32, EMB/32), 256>>>(wo, wot, EMB, EMB);
    transpose_h<<<dim3(EMB/32, FFD/32), 256>>>(w1, w1t, EMB, FFD);
    transpose_h<<<dim3(FFD/32, EMB/32), 256>>>(w2, w2t, FFD, EMB);
    {
        int n4 = MROWS * EMB / 4;
        cvt3<<<(n4 + 255) / 256, 256>>>(value, key, query, hval, hkey, hqry, n4);
    }

    dim3 gProj(EMB / 128, MROWS / 128);   // (4, 256)
    dim3 gFF1 (FFD / 128, MROWS / 128);   // (8, 256)
    dim3 gFF2 (EMB / 128, MROWS / 128);

    // QKV projections (fp16 out)
    hgemm<1,0><<<gProj, 256, HG_SMEM>>>(hval, wvt, bv, hv, MROWS, EMB, EMB);
    hgemm<1,0><<<gProj, 256, HG_SMEM>>>(hkey, wkt, bk, hk, MROWS, EMB, EMB);
    hgemm<1,0><<<gProj, 256, HG_SMEM>>>(hqry, wqt, bq, hq, MROWS, EMB, EMB);

    // block attention (fp16)
    dim3 gAtt(HEADS, ABLK, NB);
    attn_h<<<gAtt, 256, ATT_SMEM>>>(hq, hk, hv, mask, hatt);

    // output projection (fp32 out) + LN1 (fp32 + fp16 outs)
    hgemm<0,0><<<gProj, 256, HG_SMEM>>>(hatt, wot, bo, gtmp, MROWS, EMB, EMB);
    ln_kernel<1><<<MROWS, 128>>>(gtmp, query, g1, b1, gx, hx);

    // FFN + LN2
    hgemm<1,1><<<gFF1, 256, HG_SMEM>>>(hx, w1t, bf1, hff, MROWS, FFD, EMB);
    hgemm<0,0><<<gFF2, 256, HG_SMEM>>>(hff, w2t, bf2, gtmp, MROWS, EMB, FFD);
    ln_kernel<0><<<MROWS, 128>>>(gtmp, gx, g2, b2, out, nullptr);
}